// round 5
// baseline (speedup 1.0000x reference)
#include <cuda_runtime.h>
#include <cuda_fp16.h>
#include <cstdint>

#define WINDOW   128
#define EDIM     64
#define SEQQ     4096
#define NWIN     32
#define THREADS  256
#define SCALE    0.125f

// padded smem row stride (halves): 144B stride -> ldmatrix row ptrs land on
// distinct 4-bank groups -> conflict-free (validated R4)
#define RS 72

// smem layout (half units): Q[256 rows], K[384 rows], V[384 rows]
#define O_Q  0
#define O_K  (O_Q + 256 * RS)
#define O_V  (O_K + 384 * RS)
#define SMEM_HALVES (O_V + 384 * RS)       // 1024*72
#define SMEM_BYTES  (SMEM_HALVES * 2)      // 147456

__device__ __forceinline__ void mma16816(float* c, const uint32_t* a, const uint32_t* b) {
    asm volatile(
        "mma.sync.aligned.m16n8k16.row.col.f32.f16.f16.f32 "
        "{%0,%1,%2,%3}, {%4,%5,%6,%7}, {%8,%9}, {%0,%1,%2,%3};"
        : "+f"(c[0]), "+f"(c[1]), "+f"(c[2]), "+f"(c[3])
        : "r"(a[0]), "r"(a[1]), "r"(a[2]), "r"(a[3]), "r"(b[0]), "r"(b[1]));
}
__device__ __forceinline__ void ldm_x4(uint32_t* r, uint32_t addr) {
    asm volatile("ldmatrix.sync.aligned.m8n8.x4.shared.b16 {%0,%1,%2,%3}, [%4];"
        : "=r"(r[0]), "=r"(r[1]), "=r"(r[2]), "=r"(r[3]) : "r"(addr));
}
__device__ __forceinline__ void ldm_x4_t(uint32_t* r, uint32_t addr) {
    asm volatile("ldmatrix.sync.aligned.m8n8.x4.trans.shared.b16 {%0,%1,%2,%3}, [%4];"
        : "=r"(r[0]), "=r"(r[1]), "=r"(r[2]), "=r"(r[3]) : "r"(addr));
}
__device__ __forceinline__ uint32_t smem_u32(const void* p) {
    uint32_t a;
    asm("{ .reg .u64 t; cvta.to.shared.u64 t, %1; cvt.u32.u64 %0, t; }" : "=r"(a) : "l"(p));
    return a;
}
__device__ __forceinline__ uint32_t pack_h2(float x, float y) {
    __half2 h = __floats2half2_rn(x, y);
    return *reinterpret_cast<uint32_t*>(&h);
}

__global__ __launch_bounds__(THREADS, 1)
void lattn_hmma(const float* __restrict__ q, const float* __restrict__ k,
                const float* __restrict__ v, float* __restrict__ out)
{
    extern __shared__ __half smem[];
    const uint32_t sb  = smem_u32(smem);
    const uint32_t sbQ = sb;
    const uint32_t sbK = sb + O_K * 2;
    const uint32_t sbV = sb + O_V * 2;

    const int tid = threadIdx.x;
    const int w   = tid >> 5;
    const int ln  = tid & 31;
    const int g   = ln >> 2;
    const int tig = ln & 3;
    const int h   = w >> 2;            // window within pair (0/1)
    const int m   = w & 3;             // row-quarter within window
    const int pr  = blockIdx.x;        // window-pair index 0..15
    const int bh  = blockIdx.y;
    const bool first = (pr == 0);

    const long long qrow0 = (long long)bh * SEQQ + (long long)pr * 256;
    const long long krow0 = qrow0 - WINDOW;     // staged key row 0

    // ---- stage Q (scaled) 256 rows, K/V 384 rows ----
    {
        const float2* qg = (const float2*)(q + qrow0 * EDIM);
        #pragma unroll
        for (int it = 0; it < 32; ++it) {
            int idx = it * THREADS + tid;
            int row = idx >> 5, c2 = idx & 31;
            float2 f = qg[idx];
            *(__half2*)&smem[O_Q + row * RS + 2 * c2] =
                __floats2half2_rn(f.x * SCALE, f.y * SCALE);
        }
        const float2* kg = (const float2*)(k + krow0 * EDIM);
        const float2* vg = (const float2*)(v + krow0 * EDIM);
        #pragma unroll
        for (int it = 0; it < 48; ++it) {
            int idx = it * THREADS + tid;
            int row = idx >> 5, c2 = idx & 31;
            if (!first || row >= WINDOW) {
                float2 fk = kg[idx];
                float2 fv = vg[idx];
                *(__half2*)&smem[O_K + row * RS + 2 * c2] = __floats2half2_rn(fk.x, fk.y);
                *(__half2*)&smem[O_V + row * RS + 2 * c2] = __floats2half2_rn(fv.x, fv.y);
            }
        }
    }
    __syncthreads();

    // per-lane ldmatrix base offsets (bytes)
    const uint32_t koff = 2u * (((ln & 7) + ((ln & 16) >> 1)) * RS + (ln & 8));
    const uint32_t voff = 2u * (((ln & 7) + (ln & 8)) * RS + ((ln & 16) >> 1));

    const int qrow_st = h * 128 + m * 32;   // first staged q row of this warp
    const int kb      = h * 128;            // staged key base for this warp's window

    // ---- resident Q A-fragments: 2 m-tiles x 4 e-ksteps ----
    uint32_t qa[2][4][4];
    {
        const uint32_t qbase = sbQ + 2u * qrow_st * RS + voff;
        #pragma unroll
        for (int mt = 0; mt < 2; ++mt)
            #pragma unroll
            for (int ks = 0; ks < 4; ++ks)
                ldm_x4(qa[mt][ks], qbase + 2u * (16 * mt * RS + 16 * ks));
    }

    float o[2][8][4];
    #pragma unroll
    for (int mt = 0; mt < 2; ++mt)
        #pragma unroll
        for (int nt = 0; nt < 8; ++nt)
            #pragma unroll
            for (int i = 0; i < 4; ++i) o[mt][nt][i] = 0.f;
    float lsum[2][2] = {{0.f, 0.f}, {0.f, 0.f}};

    const int cstart = (first && h == 0) ? 2 : 0;
    #pragma unroll
    for (int c = 0; c < 4; ++c) {
        if (c < cstart) continue;
        const int jb = 64 * c;              // key offset within this window's 256

        // ---- S chunk: both m-tiles share every K fragment ----
        float s[2][8][4];
        #pragma unroll
        for (int mt = 0; mt < 2; ++mt)
            #pragma unroll
            for (int nt = 0; nt < 8; ++nt)
                #pragma unroll
                for (int i = 0; i < 4; ++i) s[mt][nt][i] = 0.f;

        const uint32_t kcb = sbK + 2u * (kb + jb) * RS + koff;
        #pragma unroll
        for (int ks = 0; ks < 4; ++ks) {
            #pragma unroll
            for (int ntp = 0; ntp < 4; ++ntp) {
                uint32_t b[4];
                ldm_x4(b, kcb + 2u * (16 * ntp * RS + 16 * ks));
                mma16816(s[0][2 * ntp],     qa[0][ks], b);
                mma16816(s[0][2 * ntp + 1], qa[0][ks], b + 2);
                mma16816(s[1][2 * ntp],     qa[1][ks], b);
                mma16816(s[1][2 * ntp + 1], qa[1][ks], b + 2);
            }
        }

        // ---- mask + exp + row-sum, repack to A-fragments ----
        const bool domask = (c >= 2);
        uint32_t pa[2][4][4];
        #pragma unroll
        for (int mt = 0; mt < 2; ++mt) {
            const int rl   = m * 32 + mt * 16 + g;   // window-local q row
            const int lim0 = rl + WINDOW;
            const int lim1 = rl + 8 + WINDOW;
            #pragma unroll
            for (int nt = 0; nt < 8; ++nt) {
                int col0 = jb + 8 * nt + 2 * tig;
                float p0 = (!domask || col0     <= lim0) ? __expf(s[mt][nt][0]) : 0.f;
                float p1 = (!domask || col0 + 1 <= lim0) ? __expf(s[mt][nt][1]) : 0.f;
                float p2 = (!domask || col0     <= lim1) ? __expf(s[mt][nt][2]) : 0.f;
                float p3 = (!domask || col0 + 1 <= lim1) ? __expf(s[mt][nt][3]) : 0.f;
                lsum[mt][0] += p0 + p1;
                lsum[mt][1] += p2 + p3;
                s[mt][nt][0] = p0; s[mt][nt][1] = p1;
                s[mt][nt][2] = p2; s[mt][nt][3] = p3;
            }
            #pragma unroll
            for (int t = 0; t < 4; ++t) {
                pa[mt][t][0] = pack_h2(s[mt][2 * t][0],     s[mt][2 * t][1]);
                pa[mt][t][1] = pack_h2(s[mt][2 * t][2],     s[mt][2 * t][3]);
                pa[mt][t][2] = pack_h2(s[mt][2 * t + 1][0], s[mt][2 * t + 1][1]);
                pa[mt][t][3] = pack_h2(s[mt][2 * t + 1][2], s[mt][2 * t + 1][3]);
            }
        }

        // ---- PV chunk: both m-tiles share every V fragment ----
        const uint32_t vcb = sbV + 2u * (kb + jb) * RS + voff;
        #pragma unroll
        for (int t = 0; t < 4; ++t) {
            #pragma unroll
            for (int ep = 0; ep < 4; ++ep) {
                uint32_t b[4];
                ldm_x4_t(b, vcb + 2u * (16 * t * RS + 16 * ep));
                mma16816(o[0][2 * ep],     pa[0][t], b);
                mma16816(o[0][2 * ep + 1], pa[0][t], b + 2);
                mma16816(o[1][2 * ep],     pa[1][t], b);
                mma16816(o[1][2 * ep + 1], pa[1][t], b + 2);
            }
        }
    }

    // ---- reduce l over the quad, normalize, store ----
    float* ob = out + qrow0 * EDIM;
    #pragma unroll
    for (int mt = 0; mt < 2; ++mt) {
        float l0 = lsum[mt][0], l1 = lsum[mt][1];
        l0 += __shfl_xor_sync(0xFFFFFFFFu, l0, 1);
        l0 += __shfl_xor_sync(0xFFFFFFFFu, l0, 2);
        l1 += __shfl_xor_sync(0xFFFFFFFFu, l1, 1);
        l1 += __shfl_xor_sync(0xFFFFFFFFu, l1, 2);
        const float r0 = 1.f / l0;
        const float r1 = 1.f / l1;
        const int rowA = qrow_st + mt * 16 + g;
        const int rowB = rowA + 8;
        #pragma unroll
        for (int nt = 0; nt < 8; ++nt) {
            int e0 = 8 * nt + 2 * tig;
            float2 v0 = make_float2(o[mt][nt][0] * r0, o[mt][nt][1] * r0);
            float2 v1 = make_float2(o[mt][nt][2] * r1, o[mt][nt][3] * r1);
            *(float2*)&ob[(long long)rowA * EDIM + e0] = v0;
            *(float2*)&ob[(long long)rowB * EDIM + e0] = v1;
        }
    }
}

extern "C" void kernel_launch(void* const* d_in, const int* in_sizes, int n_in,
                              void* d_out, int out_size)
{
    const float* q = (const float*)d_in[0];
    const float* k = (const float*)d_in[1];
    const float* v = (const float*)d_in[2];
    float* out = (float*)d_out;

    const int bh_count = in_sizes[0] / (SEQQ * EDIM);   // b*h = 32

    cudaFuncSetAttribute(lattn_hmma, cudaFuncAttributeMaxDynamicSharedMemorySize, SMEM_BYTES);

    dim3 grid(NWIN / 2, bh_count);
    lattn_hmma<<<grid, THREADS, SMEM_BYTES>>>(q, k, v, out);
}

// round 6
// speedup vs baseline: 1.2941x; 1.2941x over previous
#include <cuda_runtime.h>
#include <cuda_fp16.h>
#include <cstdint>

#define WINDOW   128
#define EDIM     64
#define SEQQ     4096
#define NWIN     32
#define THREADS  256
// scale * log2(e): S computed directly in log2 domain, exp = ex2
#define SCALE_L2E 0.180336880f

// padded smem row stride (halves): 144B stride -> ldmatrix row ptrs land on
// distinct 4-bank groups -> conflict-free (validated R4)
#define RS 72

// smem layout (half units): Q[128], K[256], V[256] row-major [row][e]
#define O_Q  0
#define O_K  (O_Q + 128 * RS)
#define O_V  (O_K + 256 * RS)
#define SMEM_HALVES (O_V + 256 * RS)
#define SMEM_BYTES  ((SMEM_HALVES + 16) * 2)   // +pad for safety

__device__ __forceinline__ void mma16816(float* c, const uint32_t* a, const uint32_t* b) {
    asm volatile(
        "mma.sync.aligned.m16n8k16.row.col.f32.f16.f16.f32 "
        "{%0,%1,%2,%3}, {%4,%5,%6,%7}, {%8,%9}, {%0,%1,%2,%3};"
        : "+f"(c[0]), "+f"(c[1]), "+f"(c[2]), "+f"(c[3])
        : "r"(a[0]), "r"(a[1]), "r"(a[2]), "r"(a[3]), "r"(b[0]), "r"(b[1]));
}
__device__ __forceinline__ void ldm_x4(uint32_t* r, uint32_t addr) {
    asm volatile("ldmatrix.sync.aligned.m8n8.x4.shared.b16 {%0,%1,%2,%3}, [%4];"
        : "=r"(r[0]), "=r"(r[1]), "=r"(r[2]), "=r"(r[3]) : "r"(addr));
}
__device__ __forceinline__ void ldm_x4_t(uint32_t* r, uint32_t addr) {
    asm volatile("ldmatrix.sync.aligned.m8n8.x4.trans.shared.b16 {%0,%1,%2,%3}, [%4];"
        : "=r"(r[0]), "=r"(r[1]), "=r"(r[2]), "=r"(r[3]) : "r"(addr));
}
__device__ __forceinline__ void ldm_x2_t(uint32_t* r, uint32_t addr) {
    asm volatile("ldmatrix.sync.aligned.m8n8.x2.trans.shared.b16 {%0,%1}, [%2];"
        : "=r"(r[0]), "=r"(r[1]) : "r"(addr));
}
__device__ __forceinline__ uint32_t smem_u32(const void* p) {
    uint32_t a;
    asm("{ .reg .u64 t; cvta.to.shared.u64 t, %1; cvt.u32.u64 %0, t; }" : "=r"(a) : "l"(p));
    return a;
}
__device__ __forceinline__ float ex2f(float x) {
    float r;
    asm("ex2.approx.f32 %0, %1;" : "=f"(r) : "f"(x));
    return r;
}
__device__ __forceinline__ uint32_t pack_h2(float x, float y) {
    __half2 h = __floats2half2_rn(x, y);
    return *reinterpret_cast<uint32_t*>(&h);
}

__global__ __launch_bounds__(THREADS, 2)
void lattn_hmma(const float* __restrict__ q, const float* __restrict__ k,
                const float* __restrict__ v, float* __restrict__ out)
{
    extern __shared__ __half smem[];
    const uint32_t sb  = smem_u32(smem);
    const uint32_t sbQ = sb;
    const uint32_t sbK = sb + O_K * 2;
    const uint32_t sbV = sb + O_V * 2;

    const int tid = threadIdx.x;
    const int w   = tid >> 5;          // warp 0..7 -> q rows [16w, 16w+16)
    const int ln  = tid & 31;
    const int g   = ln >> 2;
    const int tig = ln & 3;
    const int win = blockIdx.x;
    const int bh  = blockIdx.y;
    const bool have_back = (win > 0);

    const long long qrow0 = (long long)bh * SEQQ + (long long)win * WINDOW;
    const long long krow0 = qrow0 - WINDOW;

    // ---- stage Q (scaled by scale*log2e), K, V row-major ----
    {
        const float2* qg = (const float2*)(q + qrow0 * EDIM);
        #pragma unroll
        for (int it = 0; it < 16; ++it) {
            int idx = it * THREADS + tid;
            int row = idx >> 5, c2 = idx & 31;
            float2 f = qg[idx];
            *(__half2*)&smem[O_Q + row * RS + 2 * c2] =
                __floats2half2_rn(f.x * SCALE_L2E, f.y * SCALE_L2E);
        }
        const float2* kg = (const float2*)(k + krow0 * EDIM);
        const float2* vg = (const float2*)(v + krow0 * EDIM);
        #pragma unroll
        for (int it = 0; it < 32; ++it) {
            int idx = it * THREADS + tid;
            int row = idx >> 5, c2 = idx & 31;
            if (have_back || row >= WINDOW) {
                float2 fk = kg[idx];
                float2 fv = vg[idx];
                *(__half2*)&smem[O_K + row * RS + 2 * c2] = __floats2half2_rn(fk.x, fk.y);
                *(__half2*)&smem[O_V + row * RS + 2 * c2] = __floats2half2_rn(fv.x, fv.y);
            }
        }
        // V ones-column at e=64 (l = P @ ones), zeros at e=65..71
        const __half2 one0 = __floats2half2_rn(1.f, 0.f);
        const __half2 zz   = __floats2half2_rn(0.f, 0.f);
        #pragma unroll
        for (int it = 0; it < 4; ++it) {
            int idx = it * THREADS + tid;    // 0..1023
            int row = idx >> 2, cc = idx & 3;
            *(__half2*)&smem[O_V + row * RS + 64 + 2 * cc] = (cc == 0) ? one0 : zz;
        }
    }
    __syncthreads();

    const int row0 = 16 * w + g;
    const int row1 = row0 + 8;

    // per-lane ldmatrix base offsets (bytes)
    const uint32_t koff  = 2u * (((ln & 7) + ((ln & 16) >> 1)) * RS + (ln & 8));
    const uint32_t voff  = 2u * (((ln & 7) + (ln & 8)) * RS + ((ln & 16) >> 1));
    const uint32_t voff2 = 2u * (((ln & 7) + (ln & 8)) * RS + 64);   // ones tile (x2)

    // ---- resident Q A-fragments (4 e-ksteps) ----
    uint32_t qa[4][4];
    {
        const uint32_t qbase = sbQ + 2u * (16 * w) * RS + voff;
        #pragma unroll
        for (int ks = 0; ks < 4; ++ks)
            ldm_x4(qa[ks], qbase + 2u * 16 * ks);
    }

    float o[8][4];
    #pragma unroll
    for (int nt = 0; nt < 8; ++nt)
        #pragma unroll
        for (int i = 0; i < 4; ++i) o[nt][i] = 0.f;
    float oL[4] = {0.f, 0.f, 0.f, 0.f};    // l accumulator tile (cols 64..71)

    const int cstart = have_back ? 0 : 2;
    const int cend   = (w < 4) ? 3 : 4;    // rows<64 have no valid keys in chunk 3
    #pragma unroll
    for (int c = 0; c < 4; ++c) {
        if (c < cstart || c >= cend) continue;
        const int jb = 64 * c;

        // ---- S chunk: Q x K^T over 64 keys ----
        float s[8][4];
        #pragma unroll
        for (int nt = 0; nt < 8; ++nt)
            #pragma unroll
            for (int i = 0; i < 4; ++i) s[nt][i] = 0.f;

        const uint32_t kcb = sbK + 2u * jb * RS + koff;
        #pragma unroll
        for (int ks = 0; ks < 4; ++ks) {
            #pragma unroll
            for (int ntp = 0; ntp < 4; ++ntp) {
                uint32_t b[4];
                ldm_x4(b, kcb + 2u * (16 * ntp * RS + 16 * ks));
                mma16816(s[2 * ntp],     qa[ks], b);
                mma16816(s[2 * ntp + 1], qa[ks], b + 2);
            }
        }

        // ---- mask + exp2 (S already in log2 domain), repack to A-fragments ----
        const bool domask = (c >= 2);
        const int lim0 = row0 + WINDOW;
        const int lim1 = row1 + WINDOW;
        uint32_t pa[4][4];
        #pragma unroll
        for (int nt = 0; nt < 8; ++nt) {
            int col0 = jb + 8 * nt + 2 * tig;
            float p0 = ex2f(s[nt][0]);
            float p1 = ex2f(s[nt][1]);
            float p2 = ex2f(s[nt][2]);
            float p3 = ex2f(s[nt][3]);
            if (domask) {
                p0 = (col0     <= lim0) ? p0 : 0.f;
                p1 = (col0 + 1 <= lim0) ? p1 : 0.f;
                p2 = (col0     <= lim1) ? p2 : 0.f;
                p3 = (col0 + 1 <= lim1) ? p3 : 0.f;
            }
            s[nt][0] = p0; s[nt][1] = p1; s[nt][2] = p2; s[nt][3] = p3;
        }
        #pragma unroll
        for (int t = 0; t < 4; ++t) {
            pa[t][0] = pack_h2(s[2 * t][0],     s[2 * t][1]);
            pa[t][1] = pack_h2(s[2 * t][2],     s[2 * t][3]);
            pa[t][2] = pack_h2(s[2 * t + 1][0], s[2 * t + 1][1]);
            pa[t][3] = pack_h2(s[2 * t + 1][2], s[2 * t + 1][3]);
        }

        // ---- PV chunk: O += P x V, plus l tile (ones column) ----
        const uint32_t vcb = sbV + 2u * jb * RS;
        #pragma unroll
        for (int t = 0; t < 4; ++t) {
            #pragma unroll
            for (int ep = 0; ep < 4; ++ep) {
                uint32_t b[4];
                ldm_x4_t(b, vcb + voff + 2u * (16 * t * RS + 16 * ep));
                mma16816(o[2 * ep],     pa[t], b);
                mma16816(o[2 * ep + 1], pa[t], b + 2);
            }
            uint32_t bl[2];
            ldm_x2_t(bl, vcb + voff2 + 2u * (16 * t * RS));
            mma16816(oL, pa[t], bl);
        }
    }

    // ---- l lives in col 64 (tig==0 lanes); broadcast, normalize, store ----
    const float l0 = __shfl_sync(0xFFFFFFFFu, oL[0], ln & 28);
    const float l1 = __shfl_sync(0xFFFFFFFFu, oL[2], ln & 28);
    const float r0 = 1.f / l0;
    const float r1 = 1.f / l1;

    float* ob = out + qrow0 * EDIM;
    #pragma unroll
    for (int nt = 0; nt < 8; ++nt) {
        int e0 = 8 * nt + 2 * tig;
        float2 v0 = make_float2(o[nt][0] * r0, o[nt][1] * r0);
        float2 v1 = make_float2(o[nt][2] * r1, o[nt][3] * r1);
        *(float2*)&ob[(long long)row0 * EDIM + e0] = v0;
        *(float2*)&ob[(long long)row1 * EDIM + e0] = v1;
    }
}

extern "C" void kernel_launch(void* const* d_in, const int* in_sizes, int n_in,
                              void* d_out, int out_size)
{
    const float* q = (const float*)d_in[0];
    const float* k = (const float*)d_in[1];
    const float* v = (const float*)d_in[2];
    float* out = (float*)d_out;

    const int bh_count = in_sizes[0] / (SEQQ * EDIM);   // b*h = 32

    cudaFuncSetAttribute(lattn_hmma, cudaFuncAttributeMaxDynamicSharedMemorySize, SMEM_BYTES);

    dim3 grid(NWIN, bh_count);
    lattn_hmma<<<grid, THREADS, SMEM_BYTES>>>(q, k, v, out);
}